// round 14
// baseline (speedup 1.0000x reference)
#include <cuda_runtime.h>
#include <cstdint>

#define TT 500
#define BB 64
#define FF 256
#define HH 512
#define OO 128

#define NCHUNK 10
#define CHLEN 50   // TT / NCHUNK

// ---- scratch (device globals: no allocation allowed) ----
__device__ float    g_xproj[(size_t)TT * BB * HH];      // 65.5 MB
__device__ unsigned g_spk[(size_t)TT * BB * (HH / 32)]; // 2 MB spike bitmasks
__device__ float    g_lin[(size_t)TT * BB * OO];        // 16 MB
__device__ float    g_woutT[HH * OO];                   // 256 KB
__device__ float    g_wrecT[HH * HH];                   // 1 MB, w_rec transposed
__device__ float    g_ytail[BB * NCHUNK * OO];          // filter chunk tails

// ============================================================
// K0a: transpose w_out [O,H] -> g_woutT [H,O]
// ============================================================
__global__ void k_wtrans(const float* __restrict__ w_out) {
    int idx = blockIdx.x * blockDim.x + threadIdx.x;
    if (idx < HH * OO) {
        int h = idx >> 7, o = idx & 127;
        g_woutT[idx] = w_out[o * HH + h];
    }
}

// ============================================================
// K0b: transpose w_rec [H,H] -> g_wrecT  (g_wrecT[j][i] = w_rec[i][j])
// ============================================================
__global__ void k_wrect(const float* __restrict__ w_rec) {
    __shared__ float tile[32][33];
    int bx = blockIdx.x * 32, by = blockIdx.y * 32;
    int tx = threadIdx.x, ty = threadIdx.y;   // 32 x 8
#pragma unroll
    for (int i = 0; i < 32; i += 8)
        tile[ty + i][tx] = w_rec[(size_t)(by + ty + i) * HH + bx + tx];
    __syncthreads();
#pragma unroll
    for (int i = 0; i < 32; i += 8)
        g_wrecT[(size_t)(bx + ty + i) * HH + by + tx] = tile[tx][ty + i];
}

// ============================================================
// K1: x_proj[m,h] = sum_f x[m,f] * w_in[h,f]  (M=32000,K=256,N=512)
// 128x128 tile, BK=16, 256 threads, 8x8 per thread
// ============================================================
__global__ void __launch_bounds__(256) k_xproj(const float* __restrict__ A,
                                               const float* __restrict__ B) {
    __shared__ float As[16][132];
    __shared__ float Bs[16][132];
    int tid = threadIdx.x;
    int tx = tid & 15, ty = tid >> 4;
    int mBase = blockIdx.x * 128;
    int nBase = blockIdx.y * 128;
    float acc[8][8] = {};
    for (int k0 = 0; k0 < FF; k0 += 16) {
#pragma unroll
        for (int i = 0; i < 2; i++) {
            int li = tid + i * 256;
            int row = li >> 2;
            int c4 = li & 3;
            float4 va = *(const float4*)(A + (size_t)(mBase + row) * FF + k0 + c4 * 4);
            As[c4 * 4 + 0][row] = va.x;
            As[c4 * 4 + 1][row] = va.y;
            As[c4 * 4 + 2][row] = va.z;
            As[c4 * 4 + 3][row] = va.w;
            float4 vb = *(const float4*)(B + (size_t)(nBase + row) * FF + k0 + c4 * 4);
            Bs[c4 * 4 + 0][row] = vb.x;
            Bs[c4 * 4 + 1][row] = vb.y;
            Bs[c4 * 4 + 2][row] = vb.z;
            Bs[c4 * 4 + 3][row] = vb.w;
        }
        __syncthreads();
#pragma unroll
        for (int k = 0; k < 16; k++) {
            float a[8], b[8];
            *(float4*)(a)     = *(const float4*)&As[k][ty * 8];
            *(float4*)(a + 4) = *(const float4*)&As[k][ty * 8 + 4];
            *(float4*)(b)     = *(const float4*)&Bs[k][tx * 8];
            *(float4*)(b + 4) = *(const float4*)&Bs[k][tx * 8 + 4];
#pragma unroll
            for (int i2 = 0; i2 < 8; i2++)
#pragma unroll
                for (int j = 0; j < 8; j++)
                    acc[i2][j] += a[i2] * b[j];
        }
        __syncthreads();
    }
#pragma unroll
    for (int i2 = 0; i2 < 8; i2++) {
        float* op = g_xproj + (size_t)(mBase + ty * 8 + i2) * HH + nBase + tx * 8;
        *(float4*)(op)     = make_float4(acc[i2][0], acc[i2][1], acc[i2][2], acc[i2][3]);
        *(float4*)(op + 4) = make_float4(acc[i2][4], acc[i2][5], acc[i2][6], acc[i2][7]);
    }
}

// ============================================================
// K2: LIF-AdEx scan — one CTA per batch, 256 threads, h = {tid, tid+256}.
// Gather restructured into batches of 8: 16 independent LDG in flight,
// adds applied in ascending-j order (bit-identical trajectory).
// ============================================================
__global__ void __launch_bounds__(256, 1)
k_scan(float* __restrict__ d_out) {
    __shared__ unsigned zsm[2][16];
    __shared__ int offs[HH];

    int tid = threadIdx.x;            // = h_a; h_b = tid + 256
    int b = blockIdx.x;               // batch
    int lane = tid & 31, warp = tid >> 5;   // warp 0..7

    const char* base_a = (const char*)g_wrecT + (size_t)tid * 4;
    const char* base_b = base_a + 256 * 4;

    float va = 0.f, ia = 0.f, aa = 0.f;
    float vb = 0.f, ib = 0.f, ab = 0.f;
    bool za = false, zb = false;

    float xa_next = g_xproj[(size_t)b * HH + tid];
    float xb_next = g_xproj[(size_t)b * HH + tid + 256];

    for (int t = 0; t < TT; t++) {
        float ra = 0.f, rb = 0.f;
        if (t > 0) {
            int buf = (t - 1) & 1;
            // ---- build offset list (all warps duplicate; benign race, same values)
            unsigned mword = (lane < 16) ? zsm[buf][lane] : 0u;
            int cnt = __popc(mword);
            int pfx = cnt;
#pragma unroll
            for (int d = 1; d < 32; d <<= 1) {
                int y = __shfl_up_sync(0xffffffffu, pfx, d);
                if (lane >= d) pfx += y;
            }
            int n = __shfl_sync(0xffffffffu, pfx, 31);
            int base = pfx - cnt;
            while (mword) {
                int bit = __ffs(mword) - 1;
                mword &= mword - 1;
                offs[base++] = ((lane << 5) + bit) << 11;   // j * 512 floats * 4B
            }
            __syncwarp();

            // ---- dense gather, 8 rows per batch: 16 independent loads in flight
            int s = 0;
            for (; s + 8 <= n; s += 8) {
                int4 o0 = *(const int4*)&offs[s];
                int4 o1 = *(const int4*)&offs[s + 4];
                float a0 = *(const float*)(base_a + o0.x);
                float a1 = *(const float*)(base_a + o0.y);
                float a2 = *(const float*)(base_a + o0.z);
                float a3 = *(const float*)(base_a + o0.w);
                float a4 = *(const float*)(base_a + o1.x);
                float a5 = *(const float*)(base_a + o1.y);
                float a6 = *(const float*)(base_a + o1.z);
                float a7 = *(const float*)(base_a + o1.w);
                float b0 = *(const float*)(base_b + o0.x);
                float b1 = *(const float*)(base_b + o0.y);
                float b2 = *(const float*)(base_b + o0.z);
                float b3 = *(const float*)(base_b + o0.w);
                float b4 = *(const float*)(base_b + o1.x);
                float b5 = *(const float*)(base_b + o1.y);
                float b6 = *(const float*)(base_b + o1.z);
                float b7 = *(const float*)(base_b + o1.w);
                // ascending-j order preserved
                ra += a0; ra += a1; ra += a2; ra += a3;
                ra += a4; ra += a5; ra += a6; ra += a7;
                rb += b0; rb += b1; rb += b2; rb += b3;
                rb += b4; rb += b5; rb += b6; rb += b7;
            }
            for (; s < n; s++) {
                int o = offs[s];
                ra += *(const float*)(base_a + o);
                rb += *(const float*)(base_b + o);
            }
        }

        float xa = xa_next, xb = xb_next;
        if (t + 1 < TT) {
            xa_next = g_xproj[(size_t)((t + 1) * BB + b) * HH + tid];
            xb_next = g_xproj[(size_t)((t + 1) * BB + b) * HH + tid + 256];
        }

        // LIF-AdEx step for h_a
        {
            float ex = expf((va - 1.0f) * 2.0f);
            float dv = 0.1f * ((((0.0f - va) + 0.5f * ex) + ia) - aa);
            float v_dec = va + dv;
            float i_dec = ia - 0.2f * ia;
            float a_dec = aa + 0.002f * (4.0f * va - aa);
            za = (v_dec - 1.0f) > 0.0f;
            va = za ? 0.0f : v_dec;
            ia = (i_dec + xa) + ra;
            aa = a_dec + (za ? 0.02f : 0.0f);
        }
        // LIF-AdEx step for h_b
        {
            float ex = expf((vb - 1.0f) * 2.0f);
            float dv = 0.1f * ((((0.0f - vb) + 0.5f * ex) + ib) - ab);
            float v_dec = vb + dv;
            float i_dec = ib - 0.2f * ib;
            float a_dec = ab + 0.002f * (4.0f * vb - ab);
            zb = (v_dec - 1.0f) > 0.0f;
            vb = zb ? 0.0f : v_dec;
            ib = (i_dec + xb) + rb;
            ab = a_dec + (zb ? 0.02f : 0.0f);
        }

        unsigned ba = __ballot_sync(0xffffffffu, za);   // word 'warp'
        unsigned bb2 = __ballot_sync(0xffffffffu, zb);  // word 'warp+8'
        if (lane == 0) {
            zsm[t & 1][warp] = ba;
            zsm[t & 1][warp + 8] = bb2;
            unsigned* gs = g_spk + (size_t)(t * BB + b) * 16;
            gs[warp] = ba;
            gs[warp + 8] = bb2;
        }
        __syncthreads();
    }

    // final states (z, v, i, a) appended after out[T,B,O]
    size_t base = (size_t)TT * BB * OO;
    size_t oa = (size_t)b * HH + tid;
    size_t ob = oa + 256;
    d_out[base + oa] = za ? 1.0f : 0.0f;
    d_out[base + ob] = zb ? 1.0f : 0.0f;
    d_out[base + BB * HH + oa] = va;
    d_out[base + BB * HH + ob] = vb;
    d_out[base + 2 * BB * HH + oa] = ia;
    d_out[base + 2 * BB * HH + ob] = ib;
    d_out[base + 3 * BB * HH + oa] = aa;
    d_out[base + 3 * BB * HH + ob] = ab;
}

// ============================================================
// K3: lin[t,b,o] = b_out[o] + sum over spiking h of w_outT[h][o]
// ============================================================
__global__ void __launch_bounds__(128) k_lin(const float* __restrict__ b_out) {
    __shared__ unsigned zw[16];
    int tb = blockIdx.x;
    int tid = threadIdx.x;
    if (tid < 16) zw[tid] = g_spk[(size_t)tb * 16 + tid];
    __syncthreads();
    float acc = 0.f;
#pragma unroll
    for (int w16 = 0; w16 < 16; w16++) {
        unsigned m = zw[w16];
        const float* wp = g_woutT + (size_t)w16 * 32 * OO + tid;
        while (m) {
            int j = __ffs(m) - 1;
            m &= m - 1;
            acc += wp[j * OO];
        }
    }
    g_lin[(size_t)tb * OO + tid] = acc + b_out[tid];
}

// ============================================================
// K4a: filter phase A — local exp-filter scan per 50-step chunk (zero init)
// ============================================================
__global__ void __launch_bounds__(128) k_filter_a(float* __restrict__ out) {
    int b = blockIdx.x;
    int c = blockIdx.y;
    int o = threadIdx.x;
    const float C = (float)(0.001 * 223.1435511314);
    float y = 0.f;
    int t0 = c * CHLEN;
    for (int t = t0; t < t0 + CHLEN; t++) {
        float l = g_lin[((size_t)t * BB + b) * OO + o];
        y = y + C * (l - y);
        out[((size_t)t * BB + b) * OO + o] = y;
    }
    g_ytail[(b * NCHUNK + c) * OO + o] = y;
}

// ============================================================
// K4b: filter phase B — add carry correction d^(k+1) * carry_c
// ============================================================
__global__ void __launch_bounds__(128) k_filter_b(float* __restrict__ out) {
    int b = blockIdx.x;
    int c = blockIdx.y + 1;
    int o = threadIdx.x;
    const float C = (float)(0.001 * 223.1435511314);
    const float D = 1.0f - C;
    float d50 = 1.0f;
    for (int i = 0; i < CHLEN; i++) d50 *= D;
    float carry = 0.f;
    for (int j = 1; j <= c; j++)
        carry = g_ytail[(b * NCHUNK + (j - 1)) * OO + o] + d50 * carry;
    int t0 = c * CHLEN;
    float p = D;
    for (int t = t0; t < t0 + CHLEN; t++) {
        out[((size_t)t * BB + b) * OO + o] += p * carry;
        p *= D;
    }
}

// ============================================================
extern "C" void kernel_launch(void* const* d_in, const int* in_sizes, int n_in,
                              void* d_out, int out_size) {
    const float* x     = (const float*)d_in[0];  // [500,64,256]
    const float* w_in  = (const float*)d_in[1];  // [512,256]
    const float* w_rec = (const float*)d_in[2];  // [512,512]
    const float* w_out = (const float*)d_in[3];  // [128,512]
    const float* b_out = (const float*)d_in[4];  // [128]
    float* out = (float*)d_out;

    k_wtrans<<<(HH * OO + 255) / 256, 256>>>(w_out);
    k_wrect<<<dim3(16, 16), dim3(32, 8)>>>(w_rec);
    k_xproj<<<dim3((TT * BB) / 128, HH / 128), 256>>>(x, w_in);
    k_scan<<<BB, 256>>>(out);
    k_lin<<<TT * BB, 128>>>(b_out);
    k_filter_a<<<dim3(BB, NCHUNK), 128>>>(out);
    k_filter_b<<<dim3(BB, NCHUNK - 1), 128>>>(out);
}

// round 15
// speedup vs baseline: 1.0138x; 1.0138x over previous
#include <cuda_runtime.h>
#include <cstdint>

#define TT 500
#define BB 64
#define FF 256
#define HH 512
#define OO 128

#define NCHUNK 10
#define CHLEN 50   // TT / NCHUNK

// ---- scratch (device globals: no allocation allowed) ----
__device__ float    g_xproj[(size_t)TT * BB * HH];      // 65.5 MB
__device__ unsigned g_spk[(size_t)TT * BB * (HH / 32)]; // 2 MB spike bitmasks
__device__ float    g_lin[(size_t)TT * BB * OO];        // 16 MB
__device__ float    g_woutT[HH * OO];                   // 256 KB
__device__ float    g_wrecT[HH * HH];                   // 1 MB, w_rec transposed
__device__ float    g_ytail[BB * NCHUNK * OO];          // filter chunk tails

// ============================================================
// K0a: transpose w_out [O,H] -> g_woutT [H,O]
// ============================================================
__global__ void k_wtrans(const float* __restrict__ w_out) {
    int idx = blockIdx.x * blockDim.x + threadIdx.x;
    if (idx < HH * OO) {
        int h = idx >> 7, o = idx & 127;
        g_woutT[idx] = w_out[o * HH + h];
    }
}

// ============================================================
// K0b: transpose w_rec [H,H] -> g_wrecT  (g_wrecT[j][i] = w_rec[i][j])
// ============================================================
__global__ void k_wrect(const float* __restrict__ w_rec) {
    __shared__ float tile[32][33];
    int bx = blockIdx.x * 32, by = blockIdx.y * 32;
    int tx = threadIdx.x, ty = threadIdx.y;   // 32 x 8
#pragma unroll
    for (int i = 0; i < 32; i += 8)
        tile[ty + i][tx] = w_rec[(size_t)(by + ty + i) * HH + bx + tx];
    __syncthreads();
#pragma unroll
    for (int i = 0; i < 32; i += 8)
        g_wrecT[(size_t)(bx + ty + i) * HH + by + tx] = tile[tx][ty + i];
}

// ============================================================
// K1: x_proj[m,h] = sum_f x[m,f] * w_in[h,f]  (M=32000,K=256,N=512)
// 128x128 tile, BK=16, 256 threads, 8x8 per thread
// ============================================================
__global__ void __launch_bounds__(256) k_xproj(const float* __restrict__ A,
                                               const float* __restrict__ B) {
    __shared__ float As[16][132];
    __shared__ float Bs[16][132];
    int tid = threadIdx.x;
    int tx = tid & 15, ty = tid >> 4;
    int mBase = blockIdx.x * 128;
    int nBase = blockIdx.y * 128;
    float acc[8][8] = {};
    for (int k0 = 0; k0 < FF; k0 += 16) {
#pragma unroll
        for (int i = 0; i < 2; i++) {
            int li = tid + i * 256;
            int row = li >> 2;
            int c4 = li & 3;
            float4 va = *(const float4*)(A + (size_t)(mBase + row) * FF + k0 + c4 * 4);
            As[c4 * 4 + 0][row] = va.x;
            As[c4 * 4 + 1][row] = va.y;
            As[c4 * 4 + 2][row] = va.z;
            As[c4 * 4 + 3][row] = va.w;
            float4 vb = *(const float4*)(B + (size_t)(nBase + row) * FF + k0 + c4 * 4);
            Bs[c4 * 4 + 0][row] = vb.x;
            Bs[c4 * 4 + 1][row] = vb.y;
            Bs[c4 * 4 + 2][row] = vb.z;
            Bs[c4 * 4 + 3][row] = vb.w;
        }
        __syncthreads();
#pragma unroll
        for (int k = 0; k < 16; k++) {
            float a[8], b[8];
            *(float4*)(a)     = *(const float4*)&As[k][ty * 8];
            *(float4*)(a + 4) = *(const float4*)&As[k][ty * 8 + 4];
            *(float4*)(b)     = *(const float4*)&Bs[k][tx * 8];
            *(float4*)(b + 4) = *(const float4*)&Bs[k][tx * 8 + 4];
#pragma unroll
            for (int i2 = 0; i2 < 8; i2++)
#pragma unroll
                for (int j = 0; j < 8; j++)
                    acc[i2][j] += a[i2] * b[j];
        }
        __syncthreads();
    }
#pragma unroll
    for (int i2 = 0; i2 < 8; i2++) {
        float* op = g_xproj + (size_t)(mBase + ty * 8 + i2) * HH + nBase + tx * 8;
        *(float4*)(op)     = make_float4(acc[i2][0], acc[i2][1], acc[i2][2], acc[i2][3]);
        *(float4*)(op + 4) = make_float4(acc[i2][4], acc[i2][5], acc[i2][6], acc[i2][7]);
    }
}

// ============================================================
// K2: LIF-AdEx scan — one CTA per batch, 256 threads, h = {tid, tid+256}.
// Gather is MANUALLY SOFTWARE-PIPELINED: batch k+1's 16 independent LDG
// issue before batch k's values are consumed, hiding L2 latency.
// Adds applied in ascending-j order (bit-identical trajectory).
// ============================================================
__global__ void __launch_bounds__(256, 1)
k_scan(float* __restrict__ d_out) {
    __shared__ unsigned zsm[2][16];
    __shared__ int offs[HH];

    int tid = threadIdx.x;            // = h_a; h_b = tid + 256
    int b = blockIdx.x;               // batch
    int lane = tid & 31, warp = tid >> 5;   // warp 0..7

    const char* base_a = (const char*)g_wrecT + (size_t)tid * 4;
    const char* base_b = base_a + 256 * 4;

    float va = 0.f, ia = 0.f, aa = 0.f;
    float vb = 0.f, ib = 0.f, ab = 0.f;
    bool za = false, zb = false;

    float xa_next = g_xproj[(size_t)b * HH + tid];
    float xb_next = g_xproj[(size_t)b * HH + tid + 256];

    for (int t = 0; t < TT; t++) {
        float ra = 0.f, rb = 0.f;
        if (t > 0) {
            int buf = (t - 1) & 1;
            // ---- build offset list (all warps duplicate; benign race, same values)
            unsigned mword = (lane < 16) ? zsm[buf][lane] : 0u;
            int cnt = __popc(mword);
            int pfx = cnt;
#pragma unroll
            for (int d = 1; d < 32; d <<= 1) {
                int y = __shfl_up_sync(0xffffffffu, pfx, d);
                if (lane >= d) pfx += y;
            }
            int n = __shfl_sync(0xffffffffu, pfx, 31);
            int base = pfx - cnt;
            while (mword) {
                int bit = __ffs(mword) - 1;
                mword &= mword - 1;
                offs[base++] = ((lane << 5) + bit) << 11;   // j * 512 floats * 4B
            }
            __syncwarp();

            // ---- software-pipelined dense gather (ascending-j add order) ----
            int s = 0;
            int nfull = n & ~7;
            if (nfull > 0) {
                int4 p0 = *(const int4*)&offs[0];
                int4 p1 = *(const int4*)&offs[4];
                float a0 = *(const float*)(base_a + p0.x);
                float a1 = *(const float*)(base_a + p0.y);
                float a2 = *(const float*)(base_a + p0.z);
                float a3 = *(const float*)(base_a + p0.w);
                float a4 = *(const float*)(base_a + p1.x);
                float a5 = *(const float*)(base_a + p1.y);
                float a6 = *(const float*)(base_a + p1.z);
                float a7 = *(const float*)(base_a + p1.w);
                float b0 = *(const float*)(base_b + p0.x);
                float b1 = *(const float*)(base_b + p0.y);
                float b2 = *(const float*)(base_b + p0.z);
                float b3 = *(const float*)(base_b + p0.w);
                float b4 = *(const float*)(base_b + p1.x);
                float b5 = *(const float*)(base_b + p1.y);
                float b6 = *(const float*)(base_b + p1.z);
                float b7 = *(const float*)(base_b + p1.w);
                for (s = 8; s < nfull; s += 8) {
                    // issue next batch's loads BEFORE consuming current batch
                    int4 q0 = *(const int4*)&offs[s];
                    int4 q1 = *(const int4*)&offs[s + 4];
                    float na0 = *(const float*)(base_a + q0.x);
                    float na1 = *(const float*)(base_a + q0.y);
                    float na2 = *(const float*)(base_a + q0.z);
                    float na3 = *(const float*)(base_a + q0.w);
                    float na4 = *(const float*)(base_a + q1.x);
                    float na5 = *(const float*)(base_a + q1.y);
                    float na6 = *(const float*)(base_a + q1.z);
                    float na7 = *(const float*)(base_a + q1.w);
                    float nb0 = *(const float*)(base_b + q0.x);
                    float nb1 = *(const float*)(base_b + q0.y);
                    float nb2 = *(const float*)(base_b + q0.z);
                    float nb3 = *(const float*)(base_b + q0.w);
                    float nb4 = *(const float*)(base_b + q1.x);
                    float nb5 = *(const float*)(base_b + q1.y);
                    float nb6 = *(const float*)(base_b + q1.z);
                    float nb7 = *(const float*)(base_b + q1.w);
                    // consume current batch (ascending j)
                    ra += a0; ra += a1; ra += a2; ra += a3;
                    ra += a4; ra += a5; ra += a6; ra += a7;
                    rb += b0; rb += b1; rb += b2; rb += b3;
                    rb += b4; rb += b5; rb += b6; rb += b7;
                    // rotate
                    a0 = na0; a1 = na1; a2 = na2; a3 = na3;
                    a4 = na4; a5 = na5; a6 = na6; a7 = na7;
                    b0 = nb0; b1 = nb1; b2 = nb2; b3 = nb3;
                    b4 = nb4; b5 = nb5; b6 = nb6; b7 = nb7;
                }
                // consume final full batch
                ra += a0; ra += a1; ra += a2; ra += a3;
                ra += a4; ra += a5; ra += a6; ra += a7;
                rb += b0; rb += b1; rb += b2; rb += b3;
                rb += b4; rb += b5; rb += b6; rb += b7;
                s = nfull;
            }
            for (; s < n; s++) {
                int o = offs[s];
                ra += *(const float*)(base_a + o);
                rb += *(const float*)(base_b + o);
            }
        }

        float xa = xa_next, xb = xb_next;
        if (t + 1 < TT) {
            xa_next = g_xproj[(size_t)((t + 1) * BB + b) * HH + tid];
            xb_next = g_xproj[(size_t)((t + 1) * BB + b) * HH + tid + 256];
        }

        // LIF-AdEx step for h_a
        {
            float ex = expf((va - 1.0f) * 2.0f);
            float dv = 0.1f * ((((0.0f - va) + 0.5f * ex) + ia) - aa);
            float v_dec = va + dv;
            float i_dec = ia - 0.2f * ia;
            float a_dec = aa + 0.002f * (4.0f * va - aa);
            za = (v_dec - 1.0f) > 0.0f;
            va = za ? 0.0f : v_dec;
            ia = (i_dec + xa) + ra;
            aa = a_dec + (za ? 0.02f : 0.0f);
        }
        // LIF-AdEx step for h_b
        {
            float ex = expf((vb - 1.0f) * 2.0f);
            float dv = 0.1f * ((((0.0f - vb) + 0.5f * ex) + ib) - ab);
            float v_dec = vb + dv;
            float i_dec = ib - 0.2f * ib;
            float a_dec = ab + 0.002f * (4.0f * vb - ab);
            zb = (v_dec - 1.0f) > 0.0f;
            vb = zb ? 0.0f : v_dec;
            ib = (i_dec + xb) + rb;
            ab = a_dec + (zb ? 0.02f : 0.0f);
        }

        unsigned ba = __ballot_sync(0xffffffffu, za);   // word 'warp'
        unsigned bb2 = __ballot_sync(0xffffffffu, zb);  // word 'warp+8'
        if (lane == 0) {
            zsm[t & 1][warp] = ba;
            zsm[t & 1][warp + 8] = bb2;
            unsigned* gs = g_spk + (size_t)(t * BB + b) * 16;
            gs[warp] = ba;
            gs[warp + 8] = bb2;
        }
        __syncthreads();
    }

    // final states (z, v, i, a) appended after out[T,B,O]
    size_t base = (size_t)TT * BB * OO;
    size_t oa = (size_t)b * HH + tid;
    size_t ob = oa + 256;
    d_out[base + oa] = za ? 1.0f : 0.0f;
    d_out[base + ob] = zb ? 1.0f : 0.0f;
    d_out[base + BB * HH + oa] = va;
    d_out[base + BB * HH + ob] = vb;
    d_out[base + 2 * BB * HH + oa] = ia;
    d_out[base + 2 * BB * HH + ob] = ib;
    d_out[base + 3 * BB * HH + oa] = aa;
    d_out[base + 3 * BB * HH + ob] = ab;
}

// ============================================================
// K3: lin[t,b,o] = b_out[o] + sum over spiking h of w_outT[h][o]
// ============================================================
__global__ void __launch_bounds__(128) k_lin(const float* __restrict__ b_out) {
    __shared__ unsigned zw[16];
    int tb = blockIdx.x;
    int tid = threadIdx.x;
    if (tid < 16) zw[tid] = g_spk[(size_t)tb * 16 + tid];
    __syncthreads();
    float acc = 0.f;
#pragma unroll
    for (int w16 = 0; w16 < 16; w16++) {
        unsigned m = zw[w16];
        const float* wp = g_woutT + (size_t)w16 * 32 * OO + tid;
        while (m) {
            int j = __ffs(m) - 1;
            m &= m - 1;
            acc += wp[j * OO];
        }
    }
    g_lin[(size_t)tb * OO + tid] = acc + b_out[tid];
}

// ============================================================
// K4a: filter phase A — local exp-filter scan per 50-step chunk (zero init)
// ============================================================
__global__ void __launch_bounds__(128) k_filter_a(float* __restrict__ out) {
    int b = blockIdx.x;
    int c = blockIdx.y;
    int o = threadIdx.x;
    const float C = (float)(0.001 * 223.1435511314);
    float y = 0.f;
    int t0 = c * CHLEN;
    for (int t = t0; t < t0 + CHLEN; t++) {
        float l = g_lin[((size_t)t * BB + b) * OO + o];
        y = y + C * (l - y);
        out[((size_t)t * BB + b) * OO + o] = y;
    }
    g_ytail[(b * NCHUNK + c) * OO + o] = y;
}

// ============================================================
// K4b: filter phase B — add carry correction d^(k+1) * carry_c
// ============================================================
__global__ void __launch_bounds__(128) k_filter_b(float* __restrict__ out) {
    int b = blockIdx.x;
    int c = blockIdx.y + 1;
    int o = threadIdx.x;
    const float C = (float)(0.001 * 223.1435511314);
    const float D = 1.0f - C;
    float d50 = 1.0f;
    for (int i = 0; i < CHLEN; i++) d50 *= D;
    float carry = 0.f;
    for (int j = 1; j <= c; j++)
        carry = g_ytail[(b * NCHUNK + (j - 1)) * OO + o] + d50 * carry;
    int t0 = c * CHLEN;
    float p = D;
    for (int t = t0; t < t0 + CHLEN; t++) {
        out[((size_t)t * BB + b) * OO + o] += p * carry;
        p *= D;
    }
}

// ============================================================
extern "C" void kernel_launch(void* const* d_in, const int* in_sizes, int n_in,
                              void* d_out, int out_size) {
    const float* x     = (const float*)d_in[0];  // [500,64,256]
    const float* w_in  = (const float*)d_in[1];  // [512,256]
    const float* w_rec = (const float*)d_in[2];  // [512,512]
    const float* w_out = (const float*)d_in[3];  // [128,512]
    const float* b_out = (const float*)d_in[4];  // [128]
    float* out = (float*)d_out;

    k_wtrans<<<(HH * OO + 255) / 256, 256>>>(w_out);
    k_wrect<<<dim3(16, 16), dim3(32, 8)>>>(w_rec);
    k_xproj<<<dim3((TT * BB) / 128, HH / 128), 256>>>(x, w_in);
    k_scan<<<BB, 256>>>(out);
    k_lin<<<TT * BB, 128>>>(b_out);
    k_filter_a<<<dim3(BB, NCHUNK), 128>>>(out);
    k_filter_b<<<dim3(BB, NCHUNK - 1), 128>>>(out);
}

// round 17
// speedup vs baseline: 1.0813x; 1.0666x over previous
#include <cuda_runtime.h>
#include <cstdint>

#define TT 500
#define BB 64
#define FF 256
#define HH 512
#define OO 128

#define NCHUNK 10
#define CHLEN 50   // TT / NCHUNK

#define ZOFF (512 * 2048)   // byte offset of the all-zero padding row in g_wrecT

// ---- scratch (device globals: no allocation allowed) ----
__device__ float    g_xproj[(size_t)TT * BB * HH];      // 65.5 MB
__device__ unsigned g_spk[(size_t)TT * BB * (HH / 32)]; // 2 MB spike bitmasks
__device__ float    g_lin[(size_t)TT * BB * OO];        // 16 MB
__device__ float    g_woutT[HH * OO];                   // 256 KB
__device__ float    g_wrecT[(HH + 1) * HH];             // w_rec^T + one zero row
__device__ float    g_ytail[BB * NCHUNK * OO];          // filter chunk tails

// ============================================================
// K0a: transpose w_out [O,H] -> g_woutT [H,O]
// ============================================================
__global__ void k_wtrans(const float* __restrict__ w_out) {
    int idx = blockIdx.x * blockDim.x + threadIdx.x;
    if (idx < HH * OO) {
        int h = idx >> 7, o = idx & 127;
        g_woutT[idx] = w_out[o * HH + h];
    }
}

// ============================================================
// K0b: transpose w_rec [H,H] -> g_wrecT  (g_wrecT[j][i] = w_rec[i][j])
// ============================================================
__global__ void k_wrect(const float* __restrict__ w_rec) {
    __shared__ float tile[32][33];
    int bx = blockIdx.x * 32, by = blockIdx.y * 32;
    int tx = threadIdx.x, ty = threadIdx.y;   // 32 x 8
#pragma unroll
    for (int i = 0; i < 32; i += 8)
        tile[ty + i][tx] = w_rec[(size_t)(by + ty + i) * HH + bx + tx];
    __syncthreads();
#pragma unroll
    for (int i = 0; i < 32; i += 8)
        g_wrecT[(size_t)(bx + ty + i) * HH + by + tx] = tile[tx][ty + i];
}

// K0c: zero padding row (row index 512)
__global__ void k_wzero() {
    g_wrecT[(size_t)HH * HH + threadIdx.x] = 0.0f;
}

// ============================================================
// K1: x_proj[m,h] = sum_f x[m,f] * w_in[h,f]  (M=32000,K=256,N=512)
// 128x128 tile, BK=16, 256 threads, 8x8 per thread
// ============================================================
__global__ void __launch_bounds__(256) k_xproj(const float* __restrict__ A,
                                               const float* __restrict__ B) {
    __shared__ float As[16][132];
    __shared__ float Bs[16][132];
    int tid = threadIdx.x;
    int tx = tid & 15, ty = tid >> 4;
    int mBase = blockIdx.x * 128;
    int nBase = blockIdx.y * 128;
    float acc[8][8] = {};
    for (int k0 = 0; k0 < FF; k0 += 16) {
#pragma unroll
        for (int i = 0; i < 2; i++) {
            int li = tid + i * 256;
            int row = li >> 2;
            int c4 = li & 3;
            float4 va = *(const float4*)(A + (size_t)(mBase + row) * FF + k0 + c4 * 4);
            As[c4 * 4 + 0][row] = va.x;
            As[c4 * 4 + 1][row] = va.y;
            As[c4 * 4 + 2][row] = va.z;
            As[c4 * 4 + 3][row] = va.w;
            float4 vb = *(const float4*)(B + (size_t)(nBase + row) * FF + k0 + c4 * 4);
            Bs[c4 * 4 + 0][row] = vb.x;
            Bs[c4 * 4 + 1][row] = vb.y;
            Bs[c4 * 4 + 2][row] = vb.z;
            Bs[c4 * 4 + 3][row] = vb.w;
        }
        __syncthreads();
#pragma unroll
        for (int k = 0; k < 16; k++) {
            float a[8], b[8];
            *(float4*)(a)     = *(const float4*)&As[k][ty * 8];
            *(float4*)(a + 4) = *(const float4*)&As[k][ty * 8 + 4];
            *(float4*)(b)     = *(const float4*)&Bs[k][tx * 8];
            *(float4*)(b + 4) = *(const float4*)&Bs[k][tx * 8 + 4];
#pragma unroll
            for (int i2 = 0; i2 < 8; i2++)
#pragma unroll
                for (int j = 0; j < 8; j++)
                    acc[i2][j] += a[i2] * b[j];
        }
        __syncthreads();
    }
#pragma unroll
    for (int i2 = 0; i2 < 8; i2++) {
        float* op = g_xproj + (size_t)(mBase + ty * 8 + i2) * HH + nBase + tx * 8;
        *(float4*)(op)     = make_float4(acc[i2][0], acc[i2][1], acc[i2][2], acc[i2][3]);
        *(float4*)(op + 4) = make_float4(acc[i2][4], acc[i2][5], acc[i2][6], acc[i2][7]);
    }
}

// Morton spread: 16-bit value -> even bit positions of 32-bit word
__device__ __forceinline__ unsigned spread16(unsigned x) {
    x &= 0xFFFFu;
    x = (x | (x << 8)) & 0x00FF00FFu;
    x = (x | (x << 4)) & 0x0F0F0F0Fu;
    x = (x | (x << 2)) & 0x33333333u;
    x = (x | (x << 1)) & 0x55555555u;
    return x;
}

// Load one batch of 8 spiked rows (float2 each) into buffer array P
#define LOADB(P, S) { \
    int4 o0 = *(const int4*)&offs[S]; \
    int4 o1 = *(const int4*)&offs[(S) + 4]; \
    P[0] = *(const float2*)(bp + o0.x); \
    P[1] = *(const float2*)(bp + o0.y); \
    P[2] = *(const float2*)(bp + o0.z); \
    P[3] = *(const float2*)(bp + o0.w); \
    P[4] = *(const float2*)(bp + o1.x); \
    P[5] = *(const float2*)(bp + o1.y); \
    P[6] = *(const float2*)(bp + o1.z); \
    P[7] = *(const float2*)(bp + o1.w); }

// Consume buffer array P in ascending-j order
#define CONSB(P) { \
    ra += P[0].x; rb += P[0].y; ra += P[1].x; rb += P[1].y; \
    ra += P[2].x; rb += P[2].y; ra += P[3].x; rb += P[3].y; \
    ra += P[4].x; rb += P[4].y; ra += P[5].x; rb += P[5].y; \
    ra += P[6].x; rb += P[6].y; ra += P[7].x; rb += P[7].y; }

// ============================================================
// K2: LIF-AdEx scan — one CTA per batch, 256 threads.
// Thread t owns ADJACENT h = {2t, 2t+1} -> one LDG.64 per spiked row.
// Depth-4 static-buffer pipeline (no register rotation) keeps ~28
// loads in flight per warp, reaching the LDG issue floor.
// Offset list zero-row padded to a multiple of 32 (x+0.0f is exact).
// Spike words re-encoded to standard layout via Morton interleave.
// ============================================================
__global__ void __launch_bounds__(256, 1)
k_scan(float* __restrict__ d_out) {
    __shared__ unsigned zsm[2][16];
    __shared__ int offs[HH];

    int tid = threadIdx.x;            // owns h = 2*tid, 2*tid+1
    int b = blockIdx.x;               // batch
    int lane = tid & 31, warp = tid >> 5;   // warp 0..7

    const char* bp = (const char*)g_wrecT + (size_t)tid * 8;

    float va = 0.f, ia = 0.f, aa = 0.f;
    float vb = 0.f, ib = 0.f, ab = 0.f;
    bool za = false, zb = false;

    float2 xp_next = *(const float2*)(g_xproj + (size_t)b * HH + 2 * tid);

    for (int t = 0; t < TT; t++) {
        float ra = 0.f, rb = 0.f;
        if (t > 0) {
            int buf = (t - 1) & 1;
            // ---- build offset list (every warp duplicates; benign race)
            unsigned mword = (lane < 16) ? zsm[buf][lane] : 0u;
            int cnt = __popc(mword);
            int pfx = cnt;
#pragma unroll
            for (int d = 1; d < 32; d <<= 1) {
                int y = __shfl_up_sync(0xffffffffu, pfx, d);
                if (lane >= d) pfx += y;
            }
            int n = __shfl_sync(0xffffffffu, pfx, 31);
            int base = pfx - cnt;
            while (mword) {
                int bit = __ffs(mword) - 1;
                mword &= mword - 1;
                offs[base++] = ((lane << 5) + bit) << 11;   // j * 2048 bytes
            }
            if (n > 0) {
                int npad = (n + 31) & ~31;
                for (int i = n + lane; i < npad; i += 32) offs[i] = ZOFF;
                __syncwarp();

                float2 A[8], B[8], C[8], D[8];
                LOADB(A, 0)
                LOADB(B, 8)
                LOADB(C, 16)
                LOADB(D, 24)
                for (int s = 32; s < npad; s += 32) {
                    CONSB(A) LOADB(A, s)
                    CONSB(B) LOADB(B, s + 8)
                    CONSB(C) LOADB(C, s + 16)
                    CONSB(D) LOADB(D, s + 24)
                }
                CONSB(A)
                CONSB(B)
                CONSB(C)
                CONSB(D)
            }
        }

        float2 xp = xp_next;
        if (t + 1 < TT)
            xp_next = *(const float2*)(g_xproj + (size_t)((t + 1) * BB + b) * HH + 2 * tid);

        // LIF-AdEx step for h = 2t
        {
            float ex = expf((va - 1.0f) * 2.0f);
            float dv = 0.1f * ((((0.0f - va) + 0.5f * ex) + ia) - aa);
            float v_dec = va + dv;
            float i_dec = ia - 0.2f * ia;
            float a_dec = aa + 0.002f * (4.0f * va - aa);
            za = (v_dec - 1.0f) > 0.0f;
            va = za ? 0.0f : v_dec;
            ia = (i_dec + xp.x) + ra;
            aa = a_dec + (za ? 0.02f : 0.0f);
        }
        // LIF-AdEx step for h = 2t+1
        {
            float ex = expf((vb - 1.0f) * 2.0f);
            float dv = 0.1f * ((((0.0f - vb) + 0.5f * ex) + ib) - ab);
            float v_dec = vb + dv;
            float i_dec = ib - 0.2f * ib;
            float a_dec = ab + 0.002f * (4.0f * vb - ab);
            zb = (v_dec - 1.0f) > 0.0f;
            vb = zb ? 0.0f : v_dec;
            ib = (i_dec + xp.y) + rb;
            ab = a_dec + (zb ? 0.02f : 0.0f);
        }

        unsigned ba = __ballot_sync(0xffffffffu, za);   // bit l: h = 64*warp + 2l
        unsigned bb2 = __ballot_sync(0xffffffffu, zb);  // bit l: h = 64*warp + 2l+1
        if (lane == 0) {
            // standard layout: word k covers h in [32k, 32k+32)
            unsigned we = spread16(ba) | (spread16(bb2) << 1);
            unsigned wo = spread16(ba >> 16) | (spread16(bb2 >> 16) << 1);
            zsm[t & 1][2 * warp] = we;
            zsm[t & 1][2 * warp + 1] = wo;
            unsigned* gs = g_spk + (size_t)(t * BB + b) * 16;
            gs[2 * warp] = we;
            gs[2 * warp + 1] = wo;
        }
        __syncthreads();
    }

    // final states (z, v, i, a) appended after out[T,B,O]
    size_t base = (size_t)TT * BB * OO;
    size_t off2 = (size_t)b * HH + 2 * tid;
    *(float2*)(d_out + base + off2) = make_float2(za ? 1.0f : 0.0f, zb ? 1.0f : 0.0f);
    *(float2*)(d_out + base + BB * HH + off2) = make_float2(va, vb);
    *(float2*)(d_out + base + 2 * BB * HH + off2) = make_float2(ia, ib);
    *(float2*)(d_out + base + 3 * BB * HH + off2) = make_float2(aa, ab);
}

// ============================================================
// K3: lin[t,b,o] = b_out[o] + sum over spiking h of w_outT[h][o]
// ============================================================
__global__ void __launch_bounds__(128) k_lin(const float* __restrict__ b_out) {
    __shared__ unsigned zw[16];
    int tb = blockIdx.x;
    int tid = threadIdx.x;
    if (tid < 16) zw[tid] = g_spk[(size_t)tb * 16 + tid];
    __syncthreads();
    float acc = 0.f;
#pragma unroll
    for (int w16 = 0; w16 < 16; w16++) {
        unsigned m = zw[w16];
        const float* wp = g_woutT + (size_t)w16 * 32 * OO + tid;
        while (m) {
            int j = __ffs(m) - 1;
            m &= m - 1;
            acc += wp[j * OO];
        }
    }
    g_lin[(size_t)tb * OO + tid] = acc + b_out[tid];
}

// ============================================================
// K4a: filter phase A — local exp-filter scan per 50-step chunk (zero init)
// ============================================================
__global__ void __launch_bounds__(128) k_filter_a(float* __restrict__ out) {
    int b = blockIdx.x;
    int c = blockIdx.y;
    int o = threadIdx.x;
    const float C = (float)(0.001 * 223.1435511314);
    float y = 0.f;
    int t0 = c * CHLEN;
    for (int t = t0; t < t0 + CHLEN; t++) {
        float l = g_lin[((size_t)t * BB + b) * OO + o];
        y = y + C * (l - y);
        out[((size_t)t * BB + b) * OO + o] = y;
    }
    g_ytail[(b * NCHUNK + c) * OO + o] = y;
}

// ============================================================
// K4b: filter phase B — add carry correction d^(k+1) * carry_c
// ============================================================
__global__ void __launch_bounds__(128) k_filter_b(float* __restrict__ out) {
    int b = blockIdx.x;
    int c = blockIdx.y + 1;
    int o = threadIdx.x;
    const float C = (float)(0.001 * 223.1435511314);
    const float D = 1.0f - C;
    float d50 = 1.0f;
    for (int i = 0; i < CHLEN; i++) d50 *= D;
    float carry = 0.f;
    for (int j = 1; j <= c; j++)
        carry = g_ytail[(b * NCHUNK + (j - 1)) * OO + o] + d50 * carry;
    int t0 = c * CHLEN;
    float p = D;
    for (int t = t0; t < t0 + CHLEN; t++) {
        out[((size_t)t * BB + b) * OO + o] += p * carry;
        p *= D;
    }
}

// ============================================================
extern "C" void kernel_launch(void* const* d_in, const int* in_sizes, int n_in,
                              void* d_out, int out_size) {
    const float* x     = (const float*)d_in[0];  // [500,64,256]
    const float* w_in  = (const float*)d_in[1];  // [512,256]
    const float* w_rec = (const float*)d_in[2];  // [512,512]
    const float* w_out = (const float*)d_in[3];  // [128,512]
    const float* b_out = (const float*)d_in[4];  // [128]
    float* out = (float*)d_out;

    k_wtrans<<<(HH * OO + 255) / 256, 256>>>(w_out);
    k_wrect<<<dim3(16, 16), dim3(32, 8)>>>(w_rec);
    k_wzero<<<1, HH>>>();
    k_xproj<<<dim3((TT * BB) / 128, HH / 128), 256>>>(x, w_in);
    k_scan<<<BB, 256>>>(out);
    k_lin<<<TT * BB, 128>>>(b_out);
    k_filter_a<<<dim3(BB, NCHUNK), 128>>>(out);
    k_filter_b<<<dim3(BB, NCHUNK - 1), 128>>>(out);
}